// round 2
// baseline (speedup 1.0000x reference)
#include <cuda_runtime.h>

#define BATCH 32
#define CDIM  512
#define LSIZE 32
#define NPIX  1024   // LSIZE*LSIZE
#define HEADS 8
#define DH    64     // CDIM / HEADS
#define OC    1536   // 3*CDIM

// Scratch (device globals; no runtime allocation allowed)
__device__ float g_rp[HEADS * NPIX * DH];           //  2 MB: rp[p][m][d]
__device__ float g_q [BATCH * HEADS * NPIX * DH];   // 64 MB: q [b][p][n][d]
__device__ float g_k [BATCH * HEADS * NPIX * DH];   // 64 MB: k+rp
__device__ float g_v [BATCH * HEADS * NPIX * DH];   // 64 MB

// ---------------------------------------------------------------------------
// Kernel 1: relative position table  rp[p, h*32+w, d] = h_pos[h,0,c] + w_pos[0,w,c]
// ---------------------------------------------------------------------------
__global__ void rp_kernel(const float* __restrict__ h_pos,
                          const float* __restrict__ w_pos) {
    int i = blockIdx.x * blockDim.x + threadIdx.x;
    if (i >= HEADS * NPIX * DH) return;
    int dd = i % DH;
    int m  = (i / DH) % NPIX;
    int p  = i / (DH * NPIX);
    int h  = m / LSIZE, w = m % LSIZE;
    int c  = p * DH + dd;
    g_rp[i] = h_pos[h * CDIM + c] + w_pos[w * CDIM + c];
}

// ---------------------------------------------------------------------------
// Kernel 2: QKV GEMM. out[o, b, hw] = sum_c W[o,c] * x[b,c,hw]
// Scatters into g_q / g_k / g_v in [b,p,n,d] layout; K gets +rp fused.
// Tile: 128(o) x 64(hw) x 16(c), 256 threads, 8x4 per thread.
// ---------------------------------------------------------------------------
#define BM 128
#define BN 64
#define BK 16
#define TM 8
#define TN 4

__global__ __launch_bounds__(256) void qkv_kernel(const float* __restrict__ x,
                                                  const float* __restrict__ w) {
    __shared__ float As[BK][BM + 1];
    __shared__ float Bs[BK][BN];

    const int b   = blockIdx.z;
    const int oc0 = blockIdx.y * BM;   // within one of q/k/v (512 % 128 == 0)
    const int hw0 = blockIdx.x * BN;
    const int tid = threadIdx.x;
    const int ty  = tid / 16;          // 0..15 -> rows of 8
    const int tx  = tid % 16;          // 0..15 -> cols of 4

    float acc[TM][TN];
#pragma unroll
    for (int i = 0; i < TM; i++)
#pragma unroll
        for (int j = 0; j < TN; j++) acc[i][j] = 0.f;

    const float* xb = x + (long)b * CDIM * NPIX;

    for (int c0 = 0; c0 < CDIM; c0 += BK) {
        // Load A tile: W[oc0+r, c0+k], 128x16 floats = 512 float4, 2 per thread
#pragma unroll
        for (int l = 0; l < 2; l++) {
            int li = tid + l * 256;           // 0..511
            int r  = li >> 2;                 // 0..127
            int k4 = (li & 3) * 4;            // 0,4,8,12
            float4 a = *(const float4*)&w[(long)(oc0 + r) * CDIM + c0 + k4];
            As[k4 + 0][r] = a.x;
            As[k4 + 1][r] = a.y;
            As[k4 + 2][r] = a.z;
            As[k4 + 3][r] = a.w;
        }
        // Load B tile: x[b, c0+k, hw0+n], 16x64 floats = 256 float4, 1 per thread
        {
            int k  = tid / 16;
            int n4 = (tid % 16) * 4;
            float4 bv = *(const float4*)&xb[(long)(c0 + k) * NPIX + hw0 + n4];
            *(float4*)&Bs[k][n4] = bv;
        }
        __syncthreads();

#pragma unroll
        for (int k = 0; k < BK; k++) {
            float ar[TM], br[TN];
#pragma unroll
            for (int i = 0; i < TM; i++) ar[i] = As[k][ty * TM + i];
#pragma unroll
            for (int j = 0; j < TN; j++) br[j] = Bs[k][tx * TN + j];
#pragma unroll
            for (int i = 0; i < TM; i++)
#pragma unroll
                for (int j = 0; j < TN; j++) acc[i][j] += ar[i] * br[j];
        }
        __syncthreads();
    }

    // Epilogue: scatter to [b,p,n,d]; whole block lives in one of q/k/v
    const int which = oc0 / CDIM;  // 0=q, 1=k, 2=v
    float* dst = (which == 0) ? g_q : (which == 1) ? g_k : g_v;

#pragma unroll
    for (int i = 0; i < TM; i++) {
        int o  = oc0 + ty * TM + i;
        int oo = o % CDIM;
        int p  = oo / DH, dd = oo % DH;
#pragma unroll
        for (int j = 0; j < TN; j++) {
            int hw = hw0 + tx * TN + j;
            float v = acc[i][j];
            if (which == 1) v += g_rp[(p * NPIX + hw) * DH + dd];
            dst[(((long)(b * HEADS + p)) * NPIX + hw) * DH + dd] = v;
        }
    }
}

// ---------------------------------------------------------------------------
// Kernel 3: attention. One query row per thread, flash-style online softmax.
// Block = 128 threads = 128 queries of one (b,p). K/V streamed in 64-row tiles.
// ---------------------------------------------------------------------------
#define KT 64

__global__ __launch_bounds__(128) void attn_kernel(float* __restrict__ out) {
    __shared__ float Ks[KT][DH];
    __shared__ float Vs[KT][DH];

    const int b   = blockIdx.z;
    const int p   = blockIdx.y;
    const int qi  = blockIdx.x * 128 + threadIdx.x;
    const int tid = threadIdx.x;

    const long head_off = ((long)(b * HEADS + p)) * NPIX * DH;
    const float* qptr = g_q + head_off + (long)qi * DH;
    const float* kbase = g_k + head_off;
    const float* vbase = g_v + head_off;

    float4 qr[16];
#pragma unroll
    for (int i = 0; i < 16; i++) qr[i] = *(const float4*)&qptr[i * 4];

    float4 acc[16];
#pragma unroll
    for (int i = 0; i < 16; i++) acc[i] = make_float4(0.f, 0.f, 0.f, 0.f);

    float mrun = -1e30f, lrun = 0.f;

    for (int m0 = 0; m0 < NPIX; m0 += KT) {
        __syncthreads();
        // Load KT*DH floats (1024 float4) for each of K,V; 8 float4/thread each
        const float4* ksrc = (const float4*)(kbase + (long)m0 * DH);
        const float4* vsrc = (const float4*)(vbase + (long)m0 * DH);
#pragma unroll
        for (int l = 0; l < 8; l++) {
            int i = tid + l * 128;
            ((float4*)Ks)[i] = ksrc[i];
            ((float4*)Vs)[i] = vsrc[i];
        }
        __syncthreads();

#pragma unroll 2
        for (int m = 0; m < KT; m++) {
            // dot(q, K'[m]) with 4 partial sums for ILP
            float s0 = 0.f, s1 = 0.f, s2 = 0.f, s3 = 0.f;
            const float4* krow = (const float4*)Ks[m];
#pragma unroll
            for (int i = 0; i < 16; i++) {
                float4 kv = krow[i];
                s0 += qr[i].x * kv.x;
                s1 += qr[i].y * kv.y;
                s2 += qr[i].z * kv.z;
                s3 += qr[i].w * kv.w;
            }
            float s = (s0 + s1) + (s2 + s3);

            if (s > mrun) {  // rare after warmup; rescale accumulator
                float corr = __expf(mrun - s);
                lrun *= corr;
#pragma unroll
                for (int i = 0; i < 16; i++) {
                    acc[i].x *= corr; acc[i].y *= corr;
                    acc[i].z *= corr; acc[i].w *= corr;
                }
                mrun = s;
            }
            float pw = __expf(s - mrun);
            lrun += pw;

            const float4* vrow = (const float4*)Vs[m];
#pragma unroll
            for (int i = 0; i < 16; i++) {
                float4 vv = vrow[i];
                acc[i].x += pw * vv.x;
                acc[i].y += pw * vv.y;
                acc[i].z += pw * vv.z;
                acc[i].w += pw * vv.w;
            }
        }
    }

    // Write out[b, p*64+dd, qi]; consecutive threads -> consecutive qi (coalesced)
    float inv = 1.0f / lrun;
    float* obase = out + (long)b * CDIM * NPIX + qi;
#pragma unroll
    for (int i = 0; i < 16; i++) {
        obase[(long)(p * DH + i * 4 + 0) * NPIX] = acc[i].x * inv;
        obase[(long)(p * DH + i * 4 + 1) * NPIX] = acc[i].y * inv;
        obase[(long)(p * DH + i * 4 + 2) * NPIX] = acc[i].z * inv;
        obase[(long)(p * DH + i * 4 + 3) * NPIX] = acc[i].w * inv;
    }
}

// ---------------------------------------------------------------------------
extern "C" void kernel_launch(void* const* d_in, const int* in_sizes, int n_in,
                              void* d_out, int out_size) {
    const float* x     = (const float*)d_in[0];  // [32,512,32,32]
    const float* qkv_w = (const float*)d_in[1];  // [1536,512]
    const float* h_pos = (const float*)d_in[2];  // [32,1,512]
    const float* w_pos = (const float*)d_in[3];  // [1,32,512]
    float* out = (float*)d_out;                  // [32,512,32,32]

    rp_kernel<<<(HEADS * NPIX * DH + 255) / 256, 256>>>(h_pos, w_pos);

    dim3 g2(NPIX / BN, OC / BM, BATCH);   // 16 x 12 x 32
    qkv_kernel<<<g2, 256>>>(x, qkv_w);

    dim3 g3(NPIX / 128, HEADS, BATCH);    // 8 x 8 x 32
    attn_kernel<<<g3, 128>>>(out);
}

// round 4
// speedup vs baseline: 1.6336x; 1.6336x over previous
#include <cuda_runtime.h>

#define BATCH 32
#define CDIM  512
#define LSIZE 32
#define NPIX  1024
#define HEADS 8
#define DH    64
#define OC    1536

// Scratch, layout [b, p, d, hw] (d-major so epilogue stores + tile loads coalesce)
__device__ float g_rp[CDIM * NPIX];          //  2 MB: rp[p*64+d][hw]
__device__ float g_q [BATCH * CDIM * NPIX];  // 64 MB
__device__ float g_k [BATCH * CDIM * NPIX];  // 64 MB  (K + rp fused)
__device__ float g_v [BATCH * CDIM * NPIX];  // 64 MB

// ---------------------------------------------------------------------------
// tf32 helpers
// ---------------------------------------------------------------------------
__device__ __forceinline__ unsigned f2tf(float x) {
    unsigned r; asm("cvt.rna.tf32.f32 %0, %1;" : "=r"(r) : "f"(x)); return r;
}
__device__ __forceinline__ void split_tf(float x, float& hi, float& lo) {
    unsigned h = f2tf(x);
    float hf = __uint_as_float(h);
    hi = hf;
    lo = __uint_as_float(f2tf(x - hf));
}
__device__ __forceinline__ void mma8(float4& c, const unsigned* a, unsigned b0, unsigned b1) {
    asm volatile(
        "mma.sync.aligned.m16n8k8.row.col.f32.tf32.tf32.f32 "
        "{%0,%1,%2,%3}, {%4,%5,%6,%7}, {%8,%9}, {%0,%1,%2,%3};"
        : "+f"(c.x), "+f"(c.y), "+f"(c.z), "+f"(c.w)
        : "r"(a[0]), "r"(a[1]), "r"(a[2]), "r"(a[3]), "r"(b0), "r"(b1));
}

// ---------------------------------------------------------------------------
// Kernel 1: rp[p*64+dd][m] = h_pos[m/32, c] + w_pos[m%32, c],  c = p*64+dd
// ---------------------------------------------------------------------------
__global__ void rp_kernel(const float* __restrict__ h_pos,
                          const float* __restrict__ w_pos) {
    int i = blockIdx.x * blockDim.x + threadIdx.x;
    if (i >= CDIM * NPIX) return;
    int m = i & (NPIX - 1);
    int c = i >> 10;
    g_rp[i] = h_pos[(m >> 5) * CDIM + c] + w_pos[(m & 31) * CDIM + c];
}

// ---------------------------------------------------------------------------
// Kernel 2: QKV GEMM, tf32x3 mma. out[o, hw] = sum_c W[o,c] x[b,c,hw]
// Block tile 128(o) x 128(hw), 8 warps (4 along M x 2 along N), warp 32x64.
// ---------------------------------------------------------------------------
__global__ __launch_bounds__(256) void qkv_kernel(const float* __restrict__ x,
                                                  const float* __restrict__ wmat) {
    __shared__ float2 As2[128][18];   // [m][k-pair], BK=16 (+2 pad)
    __shared__ float2 Bs2[16][132];   // [k][n-pair]

    const int b   = blockIdx.z;
    const int oc0 = blockIdx.y * 128;
    const int hw0 = blockIdx.x * 128;
    const int tid = threadIdx.x;
    const int w   = tid >> 5, lane = tid & 31;
    const int g   = lane >> 2, tg = lane & 3;
    const int wm  = w & 3, wn = w >> 2;

    float4 acc[2][8];
#pragma unroll
    for (int i = 0; i < 2; i++)
#pragma unroll
        for (int j = 0; j < 8; j++) acc[i][j] = make_float4(0.f, 0.f, 0.f, 0.f);

    const float* xb = x + b * CDIM * NPIX;

    for (int c0 = 0; c0 < CDIM; c0 += 16) {
        // A tile: W[oc0+r][c0+k], 128x16 -> 512 float4, 2/thread
#pragma unroll
        for (int l = 0; l < 2; l++) {
            int li = tid + l * 256;
            int r  = li >> 2;
            int k4 = (li & 3) * 4;
            float4 a = *(const float4*)&wmat[(oc0 + r) * CDIM + c0 + k4];
            float h0, l0, h1, l1, h2, l2, h3, l3;
            split_tf(a.x, h0, l0); split_tf(a.y, h1, l1);
            split_tf(a.z, h2, l2); split_tf(a.w, h3, l3);
            *(float4*)&As2[r][k4]     = make_float4(h0, l0, h1, l1);
            *(float4*)&As2[r][k4 + 2] = make_float4(h2, l2, h3, l3);
        }
        // B tile: x[c0+k][hw0+n], 16x128 -> 512 float4, 2/thread
#pragma unroll
        for (int l = 0; l < 2; l++) {
            int li = tid + l * 256;
            int k  = li >> 5;
            int n4 = (li & 31) * 4;
            float4 bv = *(const float4*)&xb[(c0 + k) * NPIX + hw0 + n4];
            float h0, l0, h1, l1, h2, l2, h3, l3;
            split_tf(bv.x, h0, l0); split_tf(bv.y, h1, l1);
            split_tf(bv.z, h2, l2); split_tf(bv.w, h3, l3);
            *(float4*)&Bs2[k][n4]     = make_float4(h0, l0, h1, l1);
            *(float4*)&Bs2[k][n4 + 2] = make_float4(h2, l2, h3, l3);
        }
        __syncthreads();

#pragma unroll
        for (int h = 0; h < 2; h++) {     // two k8 steps per smem tile
            unsigned ah[2][4], al[2][4];
#pragma unroll
            for (int mt = 0; mt < 2; mt++) {
                int mr = wm * 32 + mt * 16 + g;
                float2 a0 = As2[mr][h * 8 + tg];
                float2 a1 = As2[mr + 8][h * 8 + tg];
                float2 a2 = As2[mr][h * 8 + tg + 4];
                float2 a3 = As2[mr + 8][h * 8 + tg + 4];
                ah[mt][0] = __float_as_uint(a0.x); al[mt][0] = __float_as_uint(a0.y);
                ah[mt][1] = __float_as_uint(a1.x); al[mt][1] = __float_as_uint(a1.y);
                ah[mt][2] = __float_as_uint(a2.x); al[mt][2] = __float_as_uint(a2.y);
                ah[mt][3] = __float_as_uint(a3.x); al[mt][3] = __float_as_uint(a3.y);
            }
#pragma unroll
            for (int nt = 0; nt < 8; nt++) {
                float2 b0 = Bs2[h * 8 + tg][wn * 64 + nt * 8 + g];
                float2 b1 = Bs2[h * 8 + tg + 4][wn * 64 + nt * 8 + g];
                unsigned bh0 = __float_as_uint(b0.x), bl0 = __float_as_uint(b0.y);
                unsigned bh1 = __float_as_uint(b1.x), bl1 = __float_as_uint(b1.y);
#pragma unroll
                for (int mt = 0; mt < 2; mt++) {
                    mma8(acc[mt][nt], ah[mt], bh0, bh1);
                    mma8(acc[mt][nt], ah[mt], bl0, bl1);
                    mma8(acc[mt][nt], al[mt], bh0, bh1);
                }
            }
        }
        __syncthreads();
    }

    // Epilogue: scatter to [b, p*64+dd, hw] (coalesced float2), +rp for K
    const int which = oc0 >> 9;  // 0=q, 1=k, 2=v (tile never straddles: 512%128==0)
    float* dst = (which == 0) ? g_q : (which == 1) ? g_k : g_v;

#pragma unroll
    for (int mt = 0; mt < 2; mt++)
#pragma unroll
        for (int half = 0; half < 2; half++) {
            int o    = oc0 + wm * 32 + mt * 16 + g + half * 8;
            int oo   = o & 511;                       // p*64 + dd
            int base = (b * CDIM + oo) * NPIX;
#pragma unroll
            for (int nt = 0; nt < 8; nt++) {
                int hw = hw0 + wn * 64 + nt * 8 + 2 * tg;
                float2 v = half ? make_float2(acc[mt][nt].z, acc[mt][nt].w)
                                : make_float2(acc[mt][nt].x, acc[mt][nt].y);
                if (which == 1) {
                    float2 r = *(const float2*)&g_rp[oo * NPIX + hw];
                    v.x += r.x; v.y += r.y;
                }
                *(float2*)&dst[base + hw] = v;
            }
        }
}

// ---------------------------------------------------------------------------
// Kernel 3: flash attention, tf32 mma. 128 queries/block, 8 warps x 16 rows.
// S = Q K'^T in tf32x3, P V in tf32x1.
// ---------------------------------------------------------------------------
__global__ __launch_bounds__(256) void attn_kernel(float* __restrict__ out) {
    extern __shared__ float sm[];
    float2* Kst = (float2*)sm;                 // [64 dim][132 key] (hi,lo) pairs
    float*  Vst = sm + 64 * 132 * 2;           // [64 dim][132 key] tf32-rounded
    float*  Pb  = Vst + 64 * 132;              // 8 x [16 row][132 col]

    const int b = blockIdx.z, p = blockIdx.y;
    const int tid  = threadIdx.x;
    const int w    = tid >> 5, lane = tid & 31;
    const int g    = lane >> 2, tg = lane & 3;
    const int q0   = blockIdx.x * 128;
    const int hoff = (b * HEADS + p) * DH * NPIX;
    float* Pw = Pb + w * (16 * 132);

    // Q A-fragments, hi/lo, kept in registers (8 k-tiles x 4 regs x 2)
    unsigned qh[8][4], ql[8][4];
    {
        int qr = q0 + w * 16 + g;
#pragma unroll
        for (int kt = 0; kt < 8; kt++) {
            float x0 = g_q[hoff + (kt * 8 + tg) * NPIX + qr];
            float x1 = g_q[hoff + (kt * 8 + tg) * NPIX + qr + 8];
            float x2 = g_q[hoff + (kt * 8 + tg + 4) * NPIX + qr];
            float x3 = g_q[hoff + (kt * 8 + tg + 4) * NPIX + qr + 8];
            float h, l;
            split_tf(x0, h, l); qh[kt][0] = __float_as_uint(h); ql[kt][0] = __float_as_uint(l);
            split_tf(x1, h, l); qh[kt][1] = __float_as_uint(h); ql[kt][1] = __float_as_uint(l);
            split_tf(x2, h, l); qh[kt][2] = __float_as_uint(h); ql[kt][2] = __float_as_uint(l);
            split_tf(x3, h, l); qh[kt][3] = __float_as_uint(h); ql[kt][3] = __float_as_uint(l);
        }
    }

    float4 oacc[8];
#pragma unroll
    for (int i = 0; i < 8; i++) oacc[i] = make_float4(0.f, 0.f, 0.f, 0.f);
    float mr0 = -1e30f, mr1 = -1e30f, lr0 = 0.f, lr1 = 0.f;

    for (int kv = 0; kv < NPIX; kv += 128) {
        __syncthreads();
        // Load K (hi/lo pairs) and V (tf32-rounded) tiles: [64 dim][128 key]
#pragma unroll
        for (int t = 0; t < 8; t++) {
            int i  = tid + t * 256;          // 0..2047 float4 items
            int d  = i >> 5;
            int k4 = (i & 31) * 4;
            float4 kvv = *(const float4*)&g_k[hoff + d * NPIX + kv + k4];
            float4 vvv = *(const float4*)&g_v[hoff + d * NPIX + kv + k4];
            float h0, l0, h1, l1, h2, l2, h3, l3;
            split_tf(kvv.x, h0, l0); split_tf(kvv.y, h1, l1);
            split_tf(kvv.z, h2, l2); split_tf(kvv.w, h3, l3);
            *(float4*)&Kst[d * 132 + k4]     = make_float4(h0, l0, h1, l1);
            *(float4*)&Kst[d * 132 + k4 + 2] = make_float4(h2, l2, h3, l3);
            float4 vt;
            vt.x = __uint_as_float(f2tf(vvv.x));
            vt.y = __uint_as_float(f2tf(vvv.y));
            vt.z = __uint_as_float(f2tf(vvv.z));
            vt.w = __uint_as_float(f2tf(vvv.w));
            *(float4*)&Vst[d * 132 + k4] = vt;
        }
        __syncthreads();

        // S = Q K'^T  (16 rows x 128 keys per warp), tf32x3
        float4 sacc[16];
#pragma unroll
        for (int i = 0; i < 16; i++) sacc[i] = make_float4(0.f, 0.f, 0.f, 0.f);
#pragma unroll
        for (int kt = 0; kt < 8; kt++) {
#pragma unroll
            for (int nt = 0; nt < 16; nt++) {
                float2 b0 = Kst[(kt * 8 + tg) * 132 + nt * 8 + g];
                float2 b1 = Kst[(kt * 8 + tg + 4) * 132 + nt * 8 + g];
                unsigned bh0 = __float_as_uint(b0.x), bl0 = __float_as_uint(b0.y);
                unsigned bh1 = __float_as_uint(b1.x), bl1 = __float_as_uint(b1.y);
                mma8(sacc[nt], qh[kt], bh0, bh1);
                mma8(sacc[nt], qh[kt], bl0, bl1);
                mma8(sacc[nt], ql[kt], bh0, bh1);
            }
        }

        // Online softmax (rows g and g+8 of this warp's 16)
        float rm0 = -1e30f, rm1 = -1e30f;
#pragma unroll
        for (int nt = 0; nt < 16; nt++) {
            rm0 = fmaxf(rm0, fmaxf(sacc[nt].x, sacc[nt].y));
            rm1 = fmaxf(rm1, fmaxf(sacc[nt].z, sacc[nt].w));
        }
        rm0 = fmaxf(rm0, __shfl_xor_sync(0xffffffffu, rm0, 1));
        rm0 = fmaxf(rm0, __shfl_xor_sync(0xffffffffu, rm0, 2));
        rm1 = fmaxf(rm1, __shfl_xor_sync(0xffffffffu, rm1, 1));
        rm1 = fmaxf(rm1, __shfl_xor_sync(0xffffffffu, rm1, 2));
        float nm0 = fmaxf(mr0, rm0), nm1 = fmaxf(mr1, rm1);
        float cr0 = __expf(mr0 - nm0), cr1 = __expf(mr1 - nm1);
        mr0 = nm0; mr1 = nm1;

        float s0 = 0.f, s1 = 0.f;
#pragma unroll
        for (int nt = 0; nt < 16; nt++) {
            float e0 = __expf(sacc[nt].x - nm0);
            float e1 = __expf(sacc[nt].y - nm0);
            float e2 = __expf(sacc[nt].z - nm1);
            float e3 = __expf(sacc[nt].w - nm1);
            s0 += e0 + e1; s1 += e2 + e3;
            *(float2*)&Pw[g * 132 + nt * 8 + 2 * tg] =
                make_float2(__uint_as_float(f2tf(e0)), __uint_as_float(f2tf(e1)));
            *(float2*)&Pw[(g + 8) * 132 + nt * 8 + 2 * tg] =
                make_float2(__uint_as_float(f2tf(e2)), __uint_as_float(f2tf(e3)));
        }
        s0 += __shfl_xor_sync(0xffffffffu, s0, 1);
        s0 += __shfl_xor_sync(0xffffffffu, s0, 2);
        s1 += __shfl_xor_sync(0xffffffffu, s1, 1);
        s1 += __shfl_xor_sync(0xffffffffu, s1, 2);
        lr0 = lr0 * cr0 + s0;
        lr1 = lr1 * cr1 + s1;
#pragma unroll
        for (int nt = 0; nt < 8; nt++) {
            oacc[nt].x *= cr0; oacc[nt].y *= cr0;
            oacc[nt].z *= cr1; oacc[nt].w *= cr1;
        }
        __syncwarp();

        // O += P V  (tf32x1)
#pragma unroll
        for (int kt = 0; kt < 16; kt++) {
            unsigned a[4];
            a[0] = __float_as_uint(Pw[g * 132 + kt * 8 + tg]);
            a[1] = __float_as_uint(Pw[(g + 8) * 132 + kt * 8 + tg]);
            a[2] = __float_as_uint(Pw[g * 132 + kt * 8 + tg + 4]);
            a[3] = __float_as_uint(Pw[(g + 8) * 132 + kt * 8 + tg + 4]);
#pragma unroll
            for (int nt = 0; nt < 8; nt++) {
                unsigned b0 = __float_as_uint(Vst[(nt * 8 + g) * 132 + kt * 8 + tg]);
                unsigned b1 = __float_as_uint(Vst[(nt * 8 + g) * 132 + kt * 8 + tg + 4]);
                mma8(oacc[nt], a, b0, b1);
            }
        }
    }

    // Epilogue: normalize, transpose via Pw, coalesced store out[b][p*64+d][q]
    float il0 = 1.f / lr0, il1 = 1.f / lr1;
    __syncwarp();
#pragma unroll
    for (int nt = 0; nt < 8; nt++) {
        *(float2*)&Pw[g * 132 + nt * 8 + 2 * tg] =
            make_float2(oacc[nt].x * il0, oacc[nt].y * il0);
        *(float2*)&Pw[(g + 8) * 132 + nt * 8 + 2 * tg] =
            make_float2(oacc[nt].z * il1, oacc[nt].w * il1);
    }
    __syncwarp();
    int qbase = q0 + w * 16;
#pragma unroll
    for (int rep = 0; rep < 2; rep++) {
        int d = rep * 32 + lane;
        float vals[16];
#pragma unroll
        for (int r = 0; r < 16; r++) vals[r] = Pw[r * 132 + d];
        float* op = out + (b * CDIM + p * DH + d) * NPIX + qbase;
#pragma unroll
        for (int r4 = 0; r4 < 4; r4++)
            *(float4*)&op[r4 * 4] =
                make_float4(vals[r4 * 4], vals[r4 * 4 + 1], vals[r4 * 4 + 2], vals[r4 * 4 + 3]);
    }
}

// ---------------------------------------------------------------------------
extern "C" void kernel_launch(void* const* d_in, const int* in_sizes, int n_in,
                              void* d_out, int out_size) {
    const float* x     = (const float*)d_in[0];
    const float* qkv_w = (const float*)d_in[1];
    const float* h_pos = (const float*)d_in[2];
    const float* w_pos = (const float*)d_in[3];
    float* out = (float*)d_out;

    static int smem_set = 0;
    const int attn_smem = (64 * 132 * 2 + 64 * 132 + 8 * 16 * 132) * (int)sizeof(float);
    if (!smem_set) {
        cudaFuncSetAttribute(attn_kernel, cudaFuncAttributeMaxDynamicSharedMemorySize, attn_smem);
        smem_set = 1;
    }

    rp_kernel<<<(CDIM * NPIX + 255) / 256, 256>>>(h_pos, w_pos);

    dim3 g2(NPIX / 128, OC / 128, BATCH);   // 8 x 12 x 32
    qkv_kernel<<<g2, 256>>>(x, qkv_w);

    dim3 g3(NPIX / 128, HEADS, BATCH);      // 8 x 8 x 32
    attn_kernel<<<g3, 256, attn_smem>>>(out);
}

// round 5
// speedup vs baseline: 2.6492x; 1.6217x over previous
#include <cuda_runtime.h>
#include <cuda_bf16.h>

#define BATCH 32
#define CDIM  512
#define LSIZE 32
#define NPIX  1024
#define HEADS 8
#define DH    64
#define OC    1536

// Scratch, layout [b, p, d, hw]
__device__ float g_rp[CDIM * NPIX];          //  2 MB
__device__ float g_q [BATCH * CDIM * NPIX];  // 64 MB
__device__ float g_k [BATCH * CDIM * NPIX];  // 64 MB (K + rp fused)
__device__ float g_v [BATCH * CDIM * NPIX];  // 64 MB

// ---------------------------------------------------------------------------
// helpers
// ---------------------------------------------------------------------------
__device__ __forceinline__ unsigned f2tf(float x) {
    unsigned r; asm("cvt.rna.tf32.f32 %0, %1;" : "=r"(r) : "f"(x)); return r;
}
// bf16 hi/lo split of a k-adjacent pair, packed into two b32 (elt0 in low half)
__device__ __forceinline__ void split2(float x0, float x1, unsigned& h, unsigned& l) {
    __nv_bfloat16 h0 = __float2bfloat16(x0);
    __nv_bfloat16 h1 = __float2bfloat16(x1);
    __nv_bfloat16 l0 = __float2bfloat16(x0 - __bfloat162float(h0));
    __nv_bfloat16 l1 = __float2bfloat16(x1 - __bfloat162float(h1));
    h = ((unsigned)__bfloat16_as_ushort(h1) << 16) | __bfloat16_as_ushort(h0);
    l = ((unsigned)__bfloat16_as_ushort(l1) << 16) | __bfloat16_as_ushort(l0);
}
// bf16 m16n8k16 mma
__device__ __forceinline__ void mma16(float4& c, const unsigned* a, unsigned b0, unsigned b1) {
    asm volatile(
        "mma.sync.aligned.m16n8k16.row.col.f32.bf16.bf16.f32 "
        "{%0,%1,%2,%3}, {%4,%5,%6,%7}, {%8,%9}, {%0,%1,%2,%3};"
        : "+f"(c.x), "+f"(c.y), "+f"(c.z), "+f"(c.w)
        : "r"(a[0]), "r"(a[1]), "r"(a[2]), "r"(a[3]), "r"(b0), "r"(b1));
}
// tf32 m16n8k8 mma (PV only)
__device__ __forceinline__ void mma8(float4& c, const unsigned* a, unsigned b0, unsigned b1) {
    asm volatile(
        "mma.sync.aligned.m16n8k8.row.col.f32.tf32.tf32.f32 "
        "{%0,%1,%2,%3}, {%4,%5,%6,%7}, {%8,%9}, {%0,%1,%2,%3};"
        : "+f"(c.x), "+f"(c.y), "+f"(c.z), "+f"(c.w)
        : "r"(a[0]), "r"(a[1]), "r"(a[2]), "r"(a[3]), "r"(b0), "r"(b1));
}

// ---------------------------------------------------------------------------
// Kernel 1: rp table
// ---------------------------------------------------------------------------
__global__ void rp_kernel(const float* __restrict__ h_pos,
                          const float* __restrict__ w_pos) {
    int i = blockIdx.x * blockDim.x + threadIdx.x;
    if (i >= CDIM * NPIX) return;
    int m = i & (NPIX - 1);
    int c = i >> 10;
    g_rp[i] = h_pos[(m >> 5) * CDIM + c] + w_pos[(m & 31) * CDIM + c];
}

// ---------------------------------------------------------------------------
// Kernel 2: QKV GEMM, bf16x3 mma. 128(o) x 128(hw) tile, 8 warps (4M x 2N).
// ---------------------------------------------------------------------------
__global__ __launch_bounds__(256) void qkv_kernel(const float* __restrict__ x,
                                                  const float* __restrict__ wmat) {
    __shared__ unsigned Ah[128][12], Al[128][12];   // [m][kpair 0..7], pad 12
    __shared__ unsigned Bh[8][136],  Bl[8][136];    // [kpair][n], pad 136

    const int b   = blockIdx.z;
    const int oc0 = blockIdx.y * 128;
    const int hw0 = blockIdx.x * 128;
    const int tid = threadIdx.x;
    const int w   = tid >> 5, lane = tid & 31;
    const int g   = lane >> 2, tg = lane & 3;
    const int wm  = w & 3, wn = w >> 2;

    float4 acc[2][8];
#pragma unroll
    for (int i = 0; i < 2; i++)
#pragma unroll
        for (int j = 0; j < 8; j++) acc[i][j] = make_float4(0.f, 0.f, 0.f, 0.f);

    const float* xb = x + b * CDIM * NPIX;

    for (int c0 = 0; c0 < CDIM; c0 += 16) {
        // A: W[oc0+r][c0+k4..k4+3] -> pairs along k
#pragma unroll
        for (int l = 0; l < 2; l++) {
            int li = tid + l * 256;
            int r  = li >> 2;
            int k4 = (li & 3) * 4;
            float4 a = *(const float4*)&wmat[(oc0 + r) * CDIM + c0 + k4];
            unsigned h, lo;
            split2(a.x, a.y, h, lo); Ah[r][k4 / 2]     = h; Al[r][k4 / 2]     = lo;
            split2(a.z, a.w, h, lo); Ah[r][k4 / 2 + 1] = h; Al[r][k4 / 2 + 1] = lo;
        }
        // B: x rows (c0+2j, c0+2j+1) paired vertically
        {
            int j  = tid >> 5;
            int n4 = (tid & 31) * 4;
            float4 r0 = *(const float4*)&xb[(c0 + 2 * j) * NPIX + hw0 + n4];
            float4 r1 = *(const float4*)&xb[(c0 + 2 * j + 1) * NPIX + hw0 + n4];
            unsigned h, lo;
            split2(r0.x, r1.x, h, lo); Bh[j][n4]     = h; Bl[j][n4]     = lo;
            split2(r0.y, r1.y, h, lo); Bh[j][n4 + 1] = h; Bl[j][n4 + 1] = lo;
            split2(r0.z, r1.z, h, lo); Bh[j][n4 + 2] = h; Bl[j][n4 + 2] = lo;
            split2(r0.w, r1.w, h, lo); Bh[j][n4 + 3] = h; Bl[j][n4 + 3] = lo;
        }
        __syncthreads();

        unsigned ah[2][4], al[2][4];
#pragma unroll
        for (int mt = 0; mt < 2; mt++) {
            int mr = wm * 32 + mt * 16 + g;
            ah[mt][0] = Ah[mr][tg];         al[mt][0] = Al[mr][tg];
            ah[mt][1] = Ah[mr + 8][tg];     al[mt][1] = Al[mr + 8][tg];
            ah[mt][2] = Ah[mr][tg + 4];     al[mt][2] = Al[mr][tg + 4];
            ah[mt][3] = Ah[mr + 8][tg + 4]; al[mt][3] = Al[mr + 8][tg + 4];
        }
#pragma unroll
        for (int nt = 0; nt < 8; nt++) {
            int n = wn * 64 + nt * 8 + g;
            unsigned bh0 = Bh[tg][n], bh1 = Bh[tg + 4][n];
            unsigned bl0 = Bl[tg][n], bl1 = Bl[tg + 4][n];
#pragma unroll
            for (int mt = 0; mt < 2; mt++) {
                mma16(acc[mt][nt], ah[mt], bh0, bh1);
                mma16(acc[mt][nt], ah[mt], bl0, bl1);
                mma16(acc[mt][nt], al[mt], bh0, bh1);
            }
        }
        __syncthreads();
    }

    // Epilogue: scatter to [b, p*64+dd, hw], +rp for K
    const int which = oc0 >> 9;
    float* dst = (which == 0) ? g_q : (which == 1) ? g_k : g_v;

#pragma unroll
    for (int mt = 0; mt < 2; mt++)
#pragma unroll
        for (int half = 0; half < 2; half++) {
            int o    = oc0 + wm * 32 + mt * 16 + g + half * 8;
            int oo   = o & 511;
            int base = (b * CDIM + oo) * NPIX;
#pragma unroll
            for (int nt = 0; nt < 8; nt++) {
                int hw = hw0 + wn * 64 + nt * 8 + 2 * tg;
                float2 v = half ? make_float2(acc[mt][nt].z, acc[mt][nt].w)
                                : make_float2(acc[mt][nt].x, acc[mt][nt].y);
                if (which == 1) {
                    float2 r = *(const float2*)&g_rp[oo * NPIX + hw];
                    v.x += r.x; v.y += r.y;
                }
                *(float2*)&dst[base + hw] = v;
            }
        }
}

// ---------------------------------------------------------------------------
// Kernel 3: flash attention. S = QK'^T in bf16x3, PV in tf32x1.
// 128 queries/block, 8 warps x 16 rows, 128-key tiles.
// ---------------------------------------------------------------------------
__global__ __launch_bounds__(256) void attn_kernel(float* __restrict__ out) {
    extern __shared__ float sm[];
    unsigned* Kh  = (unsigned*)sm;             // [32 dpair][136 key]
    unsigned* Kl  = Kh + 32 * 136;             // [32][136]
    float*    Vst = (float*)(Kl + 32 * 136);   // [64 d][132 key], tf32-rounded
    float*    Pb  = Vst + 64 * 132;            // 8 x [16 row][132 col]

    const int b = blockIdx.z, p = blockIdx.y;
    const int tid  = threadIdx.x;
    const int w    = tid >> 5, lane = tid & 31;
    const int g    = lane >> 2, tg = lane & 3;
    const int q0   = blockIdx.x * 128;
    const int hoff = (b * HEADS + p) * DH * NPIX;
    float* Pw = Pb + w * (16 * 132);

    // Q A-fragments (bf16 pairs along d), 4 k16-chunks
    unsigned qh[4][4], ql[4][4];
    {
        int qr = q0 + w * 16 + g;
#pragma unroll
        for (int kt = 0; kt < 4; kt++)
#pragma unroll
            for (int r = 0; r < 4; r++) {
                int row = qr + ((r & 1) ? 8 : 0);
                int dp  = kt * 8 + tg + ((r & 2) ? 4 : 0);
                float x0 = g_q[hoff + (2 * dp) * NPIX + row];
                float x1 = g_q[hoff + (2 * dp + 1) * NPIX + row];
                split2(x0, x1, qh[kt][r], ql[kt][r]);
            }
    }

    float4 oacc[8];
#pragma unroll
    for (int i = 0; i < 8; i++) oacc[i] = make_float4(0.f, 0.f, 0.f, 0.f);
    float mr0 = -1e30f, mr1 = -1e30f, lr0 = 0.f, lr1 = 0.f;

    for (int kv = 0; kv < NPIX; kv += 128) {
        __syncthreads();
        // K tile: pair d-rows (2dp, 2dp+1), bf16 hi/lo
#pragma unroll
        for (int t = 0; t < 4; t++) {
            int i  = tid + t * 256;          // 0..1023
            int dp = i >> 5;
            int k4 = (i & 31) * 4;
            float4 r0 = *(const float4*)&g_k[hoff + (2 * dp) * NPIX + kv + k4];
            float4 r1 = *(const float4*)&g_k[hoff + (2 * dp + 1) * NPIX + kv + k4];
            unsigned h, lo;
            split2(r0.x, r1.x, h, lo); Kh[dp * 136 + k4]     = h; Kl[dp * 136 + k4]     = lo;
            split2(r0.y, r1.y, h, lo); Kh[dp * 136 + k4 + 1] = h; Kl[dp * 136 + k4 + 1] = lo;
            split2(r0.z, r1.z, h, lo); Kh[dp * 136 + k4 + 2] = h; Kl[dp * 136 + k4 + 2] = lo;
            split2(r0.w, r1.w, h, lo); Kh[dp * 136 + k4 + 3] = h; Kl[dp * 136 + k4 + 3] = lo;
        }
        // V tile: tf32-rounded floats
#pragma unroll
        for (int t = 0; t < 8; t++) {
            int i  = tid + t * 256;          // 0..2047
            int d  = i >> 5;
            int k4 = (i & 31) * 4;
            float4 vv = *(const float4*)&g_v[hoff + d * NPIX + kv + k4];
            float4 vt;
            vt.x = __uint_as_float(f2tf(vv.x));
            vt.y = __uint_as_float(f2tf(vv.y));
            vt.z = __uint_as_float(f2tf(vv.z));
            vt.w = __uint_as_float(f2tf(vv.w));
            *(float4*)&Vst[d * 132 + k4] = vt;
        }
        __syncthreads();

        // S = Q K'^T, bf16x3: 4 k16-chunks x 16 n-frags x 3 mma
        float4 sacc[16];
#pragma unroll
        for (int i = 0; i < 16; i++) sacc[i] = make_float4(0.f, 0.f, 0.f, 0.f);
#pragma unroll
        for (int kt = 0; kt < 4; kt++) {
#pragma unroll
            for (int nt = 0; nt < 16; nt++) {
                int n = nt * 8 + g;
                unsigned bh0 = Kh[(kt * 8 + tg) * 136 + n];
                unsigned bh1 = Kh[(kt * 8 + tg + 4) * 136 + n];
                unsigned bl0 = Kl[(kt * 8 + tg) * 136 + n];
                unsigned bl1 = Kl[(kt * 8 + tg + 4) * 136 + n];
                mma16(sacc[nt], qh[kt], bh0, bh1);
                mma16(sacc[nt], qh[kt], bl0, bl1);
                mma16(sacc[nt], ql[kt], bh0, bh1);
            }
        }

        // Online softmax (rows g, g+8)
        float rm0 = -1e30f, rm1 = -1e30f;
#pragma unroll
        for (int nt = 0; nt < 16; nt++) {
            rm0 = fmaxf(rm0, fmaxf(sacc[nt].x, sacc[nt].y));
            rm1 = fmaxf(rm1, fmaxf(sacc[nt].z, sacc[nt].w));
        }
        rm0 = fmaxf(rm0, __shfl_xor_sync(0xffffffffu, rm0, 1));
        rm0 = fmaxf(rm0, __shfl_xor_sync(0xffffffffu, rm0, 2));
        rm1 = fmaxf(rm1, __shfl_xor_sync(0xffffffffu, rm1, 1));
        rm1 = fmaxf(rm1, __shfl_xor_sync(0xffffffffu, rm1, 2));
        float nm0 = fmaxf(mr0, rm0), nm1 = fmaxf(mr1, rm1);
        float cr0 = __expf(mr0 - nm0), cr1 = __expf(mr1 - nm1);
        mr0 = nm0; mr1 = nm1;

        float s0 = 0.f, s1 = 0.f;
#pragma unroll
        for (int nt = 0; nt < 16; nt++) {
            float e0 = __expf(sacc[nt].x - nm0);
            float e1 = __expf(sacc[nt].y - nm0);
            float e2 = __expf(sacc[nt].z - nm1);
            float e3 = __expf(sacc[nt].w - nm1);
            s0 += e0 + e1; s1 += e2 + e3;
            *(float2*)&Pw[g * 132 + nt * 8 + 2 * tg] =
                make_float2(__uint_as_float(f2tf(e0)), __uint_as_float(f2tf(e1)));
            *(float2*)&Pw[(g + 8) * 132 + nt * 8 + 2 * tg] =
                make_float2(__uint_as_float(f2tf(e2)), __uint_as_float(f2tf(e3)));
        }
        s0 += __shfl_xor_sync(0xffffffffu, s0, 1);
        s0 += __shfl_xor_sync(0xffffffffu, s0, 2);
        s1 += __shfl_xor_sync(0xffffffffu, s1, 1);
        s1 += __shfl_xor_sync(0xffffffffu, s1, 2);
        lr0 = lr0 * cr0 + s0;
        lr1 = lr1 * cr1 + s1;
#pragma unroll
        for (int nt = 0; nt < 8; nt++) {
            oacc[nt].x *= cr0; oacc[nt].y *= cr0;
            oacc[nt].z *= cr1; oacc[nt].w *= cr1;
        }
        __syncwarp();

        // O += P V (tf32x1)
#pragma unroll
        for (int kt = 0; kt < 16; kt++) {
            unsigned a[4];
            a[0] = __float_as_uint(Pw[g * 132 + kt * 8 + tg]);
            a[1] = __float_as_uint(Pw[(g + 8) * 132 + kt * 8 + tg]);
            a[2] = __float_as_uint(Pw[g * 132 + kt * 8 + tg + 4]);
            a[3] = __float_as_uint(Pw[(g + 8) * 132 + kt * 8 + tg + 4]);
#pragma unroll
            for (int nt = 0; nt < 8; nt++) {
                unsigned b0 = __float_as_uint(Vst[(nt * 8 + g) * 132 + kt * 8 + tg]);
                unsigned b1 = __float_as_uint(Vst[(nt * 8 + g) * 132 + kt * 8 + tg + 4]);
                mma8(oacc[nt], a, b0, b1);
            }
        }
    }

    // Epilogue: normalize, transpose via Pw, coalesced store
    float il0 = 1.f / lr0, il1 = 1.f / lr1;
    __syncwarp();
#pragma unroll
    for (int nt = 0; nt < 8; nt++) {
        *(float2*)&Pw[g * 132 + nt * 8 + 2 * tg] =
            make_float2(oacc[nt].x * il0, oacc[nt].y * il0);
        *(float2*)&Pw[(g + 8) * 132 + nt * 8 + 2 * tg] =
            make_float2(oacc[nt].z * il1, oacc[nt].w * il1);
    }
    __syncwarp();
    int qbase = q0 + w * 16;
#pragma unroll
    for (int rep = 0; rep < 2; rep++) {
        int d = rep * 32 + lane;
        float vals[16];
#pragma unroll
        for (int r = 0; r < 16; r++) vals[r] = Pw[r * 132 + d];
        float* op = out + (b * CDIM + p * DH + d) * NPIX + qbase;
#pragma unroll
        for (int r4 = 0; r4 < 4; r4++)
            *(float4*)&op[r4 * 4] =
                make_float4(vals[r4 * 4], vals[r4 * 4 + 1], vals[r4 * 4 + 2], vals[r4 * 4 + 3]);
    }
}

// ---------------------------------------------------------------------------
extern "C" void kernel_launch(void* const* d_in, const int* in_sizes, int n_in,
                              void* d_out, int out_size) {
    const float* x     = (const float*)d_in[0];
    const float* qkv_w = (const float*)d_in[1];
    const float* h_pos = (const float*)d_in[2];
    const float* w_pos = (const float*)d_in[3];
    float* out = (float*)d_out;

    static int smem_set = 0;
    const int attn_smem = (2 * 32 * 136 + 64 * 132 + 8 * 16 * 132) * (int)sizeof(float);
    if (!smem_set) {
        cudaFuncSetAttribute(attn_kernel, cudaFuncAttributeMaxDynamicSharedMemorySize, attn_smem);
        smem_set = 1;
    }

    rp_kernel<<<(CDIM * NPIX + 255) / 256, 256>>>(h_pos, w_pos);

    dim3 g2(NPIX / 128, OC / 128, BATCH);   // 8 x 12 x 32
    qkv_kernel<<<g2, 256>>>(x, qkv_w);

    dim3 g3(NPIX / 128, HEADS, BATCH);      // 8 x 8 x 32
    attn_kernel<<<g3, 256, attn_smem>>>(out);
}

// round 6
// speedup vs baseline: 3.2233x; 1.2167x over previous
#include <cuda_runtime.h>
#include <cuda_bf16.h>
#include <cuda_fp16.h>

#define BATCH 32
#define CDIM  512
#define LSIZE 32
#define NPIX  1024
#define HEADS 8
#define DH    64
#define OC    1536

// ---------------------------------------------------------------------------
// Device scratch (pre-split packed forms; pairs packed along the k-dim)
// ---------------------------------------------------------------------------
__device__ float    g_rp[CDIM * NPIX];                    // 2 MB
__device__ unsigned g_Wh[OC * CDIM / 2];                  // W bf16-hi pairs (c)
__device__ unsigned g_Wl[OC * CDIM / 2];                  // W bf16-lo
__device__ unsigned g_Xh[BATCH * (CDIM / 2) * NPIX];      // x bf16-hi pairs (c)
__device__ unsigned g_Xl[BATCH * (CDIM / 2) * NPIX];
__device__ unsigned g_Qh[BATCH * (CDIM / 2) * NPIX];      // Q bf16 pairs (d)
__device__ unsigned g_Ql[BATCH * (CDIM / 2) * NPIX];
__device__ unsigned g_Kh[BATCH * (CDIM / 2) * NPIX];      // K+rp bf16 pairs (d)
__device__ unsigned g_Kl[BATCH * (CDIM / 2) * NPIX];
__device__ unsigned g_Vh[BATCH * CDIM * (NPIX / 2)];      // V fp16 pairs (key)

// ---------------------------------------------------------------------------
// helpers
// ---------------------------------------------------------------------------
__device__ __forceinline__ void split2(float x0, float x1, unsigned& h, unsigned& l) {
    __nv_bfloat16 h0 = __float2bfloat16(x0);
    __nv_bfloat16 h1 = __float2bfloat16(x1);
    __nv_bfloat16 l0 = __float2bfloat16(x0 - __bfloat162float(h0));
    __nv_bfloat16 l1 = __float2bfloat16(x1 - __bfloat162float(h1));
    h = ((unsigned)__bfloat16_as_ushort(h1) << 16) | __bfloat16_as_ushort(h0);
    l = ((unsigned)__bfloat16_as_ushort(l1) << 16) | __bfloat16_as_ushort(l0);
}
__device__ __forceinline__ unsigned packh2(float x0, float x1) {
    __half2 h = __floats2half2_rn(x0, x1);   // x0 in low half
    return *(unsigned*)&h;
}
// bf16 m16n8k16
__device__ __forceinline__ void mma16(float4& c, const unsigned* a, unsigned b0, unsigned b1) {
    asm volatile(
        "mma.sync.aligned.m16n8k16.row.col.f32.bf16.bf16.f32 "
        "{%0,%1,%2,%3}, {%4,%5,%6,%7}, {%8,%9}, {%0,%1,%2,%3};"
        : "+f"(c.x), "+f"(c.y), "+f"(c.z), "+f"(c.w)
        : "r"(a[0]), "r"(a[1]), "r"(a[2]), "r"(a[3]), "r"(b0), "r"(b1));
}
// fp16 m16n8k16 (PV)
__device__ __forceinline__ void mma16f(float4& c, const unsigned* a, unsigned b0, unsigned b1) {
    asm volatile(
        "mma.sync.aligned.m16n8k16.row.col.f32.f16.f16.f32 "
        "{%0,%1,%2,%3}, {%4,%5,%6,%7}, {%8,%9}, {%0,%1,%2,%3};"
        : "+f"(c.x), "+f"(c.y), "+f"(c.z), "+f"(c.w)
        : "r"(a[0]), "r"(a[1]), "r"(a[2]), "r"(a[3]), "r"(b0), "r"(b1));
}

// ---------------------------------------------------------------------------
// Kernel 1: rp table
// ---------------------------------------------------------------------------
__global__ void rp_kernel(const float* __restrict__ h_pos,
                          const float* __restrict__ w_pos) {
    int i = blockIdx.x * blockDim.x + threadIdx.x;
    if (i >= CDIM * NPIX) return;
    int m = i & (NPIX - 1);
    int c = i >> 10;
    g_rp[i] = h_pos[(m >> 5) * CDIM + c] + w_pos[(m & 31) * CDIM + c];
}

// ---------------------------------------------------------------------------
// Prep: split W into bf16 hi/lo pairs along c.  one thread = 8 floats.
// ---------------------------------------------------------------------------
__global__ void prep_w(const float* __restrict__ wmat) {
    int i = blockIdx.x * blockDim.x + threadIdx.x;   // uint4 index, total OC*64
    if (i >= OC * 64) return;
    int o  = i >> 6;
    int c8 = (i & 63) * 8;
    float4 a = *(const float4*)&wmat[o * CDIM + c8];
    float4 b = *(const float4*)&wmat[o * CDIM + c8 + 4];
    uint4 H, L;
    split2(a.x, a.y, H.x, L.x); split2(a.z, a.w, H.y, L.y);
    split2(b.x, b.y, H.z, L.z); split2(b.z, b.w, H.w, L.w);
    ((uint4*)g_Wh)[i] = H;
    ((uint4*)g_Wl)[i] = L;
}

// ---------------------------------------------------------------------------
// Prep: split x into bf16 hi/lo pairs along c (rows 2j,2j+1 paired).
// ---------------------------------------------------------------------------
__global__ void prep_x(const float* __restrict__ x) {
    int i = blockIdx.x * blockDim.x + threadIdx.x;   // uint4 idx, total B*256*256
    if (i >= BATCH * 256 * 256) return;
    int bj  = i >> 8;                 // b*256 + j
    int hw4 = (i & 255) * 4;
    const float* r0 = &x[(bj * 2) * NPIX + hw4];     // row 2j (b folded in)
    float4 u = *(const float4*)r0;
    float4 v = *(const float4*)(r0 + NPIX);
    uint4 H, L;
    split2(u.x, v.x, H.x, L.x); split2(u.y, v.y, H.y, L.y);
    split2(u.z, v.z, H.z, L.z); split2(u.w, v.w, H.w, L.w);
    ((uint4*)g_Xh)[i] = H;
    ((uint4*)g_Xl)[i] = L;
}

// ---------------------------------------------------------------------------
// Kernel 2: QKV GEMM, bf16x3 mma from pre-split inputs.
// 128(o) x 128(hw) tile, 8 warps (4M x 2N). Epilogue writes split forms.
// ---------------------------------------------------------------------------
__global__ __launch_bounds__(256) void qkv_kernel() {
    __shared__ unsigned Ah[128][12], Al[128][12];   // kp 0..7, pad 12
    __shared__ unsigned Bh[8][136],  Bl[8][136];

    const int b   = blockIdx.z;
    const int oc0 = blockIdx.y * 128;
    const int hw0 = blockIdx.x * 128;
    const int tid = threadIdx.x;
    const int w   = tid >> 5, lane = tid & 31;
    const int g   = lane >> 2, tg = lane & 3;
    const int wm  = w & 3, wn = w >> 2;

    float4 acc[2][8];
#pragma unroll
    for (int i = 0; i < 2; i++)
#pragma unroll
        for (int j = 0; j < 8; j++) acc[i][j] = make_float4(0.f, 0.f, 0.f, 0.f);

    const int ar  = tid >> 1;          // A row 0..127
    const int ak4 = (tid & 1) * 4;     // kp offset 0/4
    const int bj  = tid >> 5;          // B kp row 0..7
    const int bn4 = (tid & 31) * 4;

    for (int cp0 = 0; cp0 < 256; cp0 += 8) {
        uint4 ha = *(const uint4*)&g_Wh[(oc0 + ar) * 256 + cp0 + ak4];
        uint4 la = *(const uint4*)&g_Wl[(oc0 + ar) * 256 + cp0 + ak4];
        Ah[ar][ak4]     = ha.x; Ah[ar][ak4 + 1] = ha.y;
        Ah[ar][ak4 + 2] = ha.z; Ah[ar][ak4 + 3] = ha.w;
        Al[ar][ak4]     = la.x; Al[ar][ak4 + 1] = la.y;
        Al[ar][ak4 + 2] = la.z; Al[ar][ak4 + 3] = la.w;
        uint4 hb = *(const uint4*)&g_Xh[(b * 256 + cp0 + bj) * NPIX + hw0 + bn4];
        uint4 lb = *(const uint4*)&g_Xl[(b * 256 + cp0 + bj) * NPIX + hw0 + bn4];
        *(uint4*)&Bh[bj][bn4] = hb;
        *(uint4*)&Bl[bj][bn4] = lb;
        __syncthreads();

        unsigned ah[2][4], al[2][4];
#pragma unroll
        for (int mt = 0; mt < 2; mt++) {
            int mr = wm * 32 + mt * 16 + g;
            ah[mt][0] = Ah[mr][tg];         al[mt][0] = Al[mr][tg];
            ah[mt][1] = Ah[mr + 8][tg];     al[mt][1] = Al[mr + 8][tg];
            ah[mt][2] = Ah[mr][tg + 4];     al[mt][2] = Al[mr][tg + 4];
            ah[mt][3] = Ah[mr + 8][tg + 4]; al[mt][3] = Al[mr + 8][tg + 4];
        }
#pragma unroll
        for (int nt = 0; nt < 8; nt++) {
            int n = wn * 64 + nt * 8 + g;
            unsigned bh0 = Bh[tg][n], bh1 = Bh[tg + 4][n];
            unsigned bl0 = Bl[tg][n], bl1 = Bl[tg + 4][n];
#pragma unroll
            for (int mt = 0; mt < 2; mt++) {
                mma16(acc[mt][nt], ah[mt], bh0, bh1);
                mma16(acc[mt][nt], ah[mt], bl0, bl1);
                mma16(acc[mt][nt], al[mt], bh0, bh1);
            }
        }
        __syncthreads();
    }

    // Epilogue: which 0=Q, 1=K(+rp), 2=V. Write split-packed global forms.
    const int which = oc0 >> 9;

#pragma unroll
    for (int mt = 0; mt < 2; mt++)
#pragma unroll
        for (int half = 0; half < 2; half++) {
            int o  = oc0 + wm * 32 + mt * 16 + g + half * 8;
            int oo = o & 511;                                // p*64 + dd
#pragma unroll
            for (int nt = 0; nt < 8; nt++) {
                int hw = hw0 + wn * 64 + nt * 8 + 2 * tg;
                float2 v = half ? make_float2(acc[mt][nt].z, acc[mt][nt].w)
                                : make_float2(acc[mt][nt].x, acc[mt][nt].y);
                if (which == 2) {
                    g_Vh[(b * 512 + oo) * 512 + (hw >> 1)] = packh2(v.x, v.y);
                } else {
                    if (which == 1) {
                        float2 r = *(const float2*)&g_rp[oo * NPIX + hw];
                        v.x += r.x; v.y += r.y;
                    }
                    // pair adjacent d-rows across lanes (g xor 1 <-> lane xor 4)
                    float px = __shfl_xor_sync(0xffffffffu, v.x, 4);
                    float py = __shfl_xor_sync(0xffffffffu, v.y, 4);
                    if (!(g & 1)) {
                        unsigned h0, l0, h1, l1;
                        split2(v.x, px, h0, l0);   // even-d in low half
                        split2(v.y, py, h1, l1);
                        unsigned* dh = which ? g_Kh : g_Qh;
                        unsigned* dl = which ? g_Kl : g_Ql;
                        int base = (b * 256 + (oo >> 1)) * NPIX + hw;
                        uint2 uh = make_uint2(h0, h1);
                        uint2 ul = make_uint2(l0, l1);
                        *(uint2*)&dh[base] = uh;
                        *(uint2*)&dl[base] = ul;
                    }
                }
            }
        }
}

// ---------------------------------------------------------------------------
// Kernel 3: flash attention. S = QK'^T bf16x3, PV fp16 (P in registers).
// 128 queries/block, 8 warps x 16 rows, 128-key tiles.
// ---------------------------------------------------------------------------
__global__ __launch_bounds__(256) void attn_kernel(float* __restrict__ out) {
    extern __shared__ unsigned smu[];
    unsigned* Khs = smu;                    // [32 dp][136 key]
    unsigned* Kls = smu + 32 * 136;
    unsigned* Vhs = smu + 2 * 32 * 136;     // [64 d][68 keypair] fp16x2

    const int b = blockIdx.z, p = blockIdx.y;
    const int tid  = threadIdx.x;
    const int w    = tid >> 5, lane = tid & 31;
    const int g    = lane >> 2, tg = lane & 3;
    const int q0   = blockIdx.x * 128;
    const int bp32 = b * 256 + p * 32;      // base of [dp] rows for this head
    const int vb   = b * 512 + p * 64;      // base of V d-rows

    // Q A-fragments straight from pre-split globals
    unsigned qh[4][4], ql[4][4];
    {
        int qr = q0 + w * 16 + g;
#pragma unroll
        for (int kt = 0; kt < 4; kt++)
#pragma unroll
            for (int r = 0; r < 4; r++) {
                int row = qr + ((r & 1) ? 8 : 0);
                int dp  = kt * 8 + tg + ((r & 2) ? 4 : 0);
                qh[kt][r] = g_Qh[(bp32 + dp) * NPIX + row];
                ql[kt][r] = g_Ql[(bp32 + dp) * NPIX + row];
            }
    }

    float4 oacc[8];
#pragma unroll
    for (int i = 0; i < 8; i++) oacc[i] = make_float4(0.f, 0.f, 0.f, 0.f);
    float mr0 = -1e30f, mr1 = -1e30f, lr0 = 0.f, lr1 = 0.f;

    for (int kv = 0; kv < NPIX; kv += 128) {
        __syncthreads();
        // K tile (pure copy, no conversion)
#pragma unroll
        for (int t = 0; t < 4; t++) {
            int i  = tid + t * 256;
            int dp = i >> 5;
            int k4 = (i & 31) * 4;
            uint4 vh = *(const uint4*)&g_Kh[(bp32 + dp) * NPIX + kv + k4];
            uint4 vl = *(const uint4*)&g_Kl[(bp32 + dp) * NPIX + kv + k4];
            *(uint4*)&Khs[dp * 136 + k4] = vh;
            *(uint4*)&Kls[dp * 136 + k4] = vl;
        }
        // V tile (fp16 pairs along key)
#pragma unroll
        for (int t = 0; t < 4; t++) {
            int i   = tid + t * 256;
            int d   = i >> 4;
            int kp4 = (i & 15) * 4;
            uint4 vv = *(const uint4*)&g_Vh[(vb + d) * 512 + (kv >> 1) + kp4];
            *(uint4*)&Vhs[d * 68 + kp4] = vv;
        }
        __syncthreads();

        // S = Q K'^T, bf16x3
        float4 sacc[16];
#pragma unroll
        for (int i = 0; i < 16; i++) sacc[i] = make_float4(0.f, 0.f, 0.f, 0.f);
#pragma unroll
        for (int kt = 0; kt < 4; kt++) {
#pragma unroll
            for (int nt = 0; nt < 16; nt++) {
                int n = nt * 8 + g;
                unsigned bh0 = Khs[(kt * 8 + tg) * 136 + n];
                unsigned bh1 = Khs[(kt * 8 + tg + 4) * 136 + n];
                unsigned bl0 = Kls[(kt * 8 + tg) * 136 + n];
                unsigned bl1 = Kls[(kt * 8 + tg + 4) * 136 + n];
                mma16(sacc[nt], qh[kt], bh0, bh1);
                mma16(sacc[nt], qh[kt], bl0, bl1);
                mma16(sacc[nt], ql[kt], bh0, bh1);
            }
        }

        // Online softmax (rows g, g+8); overwrite sacc with exp weights
        float rm0 = -1e30f, rm1 = -1e30f;
#pragma unroll
        for (int nt = 0; nt < 16; nt++) {
            rm0 = fmaxf(rm0, fmaxf(sacc[nt].x, sacc[nt].y));
            rm1 = fmaxf(rm1, fmaxf(sacc[nt].z, sacc[nt].w));
        }
        rm0 = fmaxf(rm0, __shfl_xor_sync(0xffffffffu, rm0, 1));
        rm0 = fmaxf(rm0, __shfl_xor_sync(0xffffffffu, rm0, 2));
        rm1 = fmaxf(rm1, __shfl_xor_sync(0xffffffffu, rm1, 1));
        rm1 = fmaxf(rm1, __shfl_xor_sync(0xffffffffu, rm1, 2));
        float nm0 = fmaxf(mr0, rm0), nm1 = fmaxf(mr1, rm1);
        float cr0 = __expf(mr0 - nm0), cr1 = __expf(mr1 - nm1);
        mr0 = nm0; mr1 = nm1;

        float s0 = 0.f, s1 = 0.f;
#pragma unroll
        for (int nt = 0; nt < 16; nt++) {
            sacc[nt].x = __expf(sacc[nt].x - nm0);
            sacc[nt].y = __expf(sacc[nt].y - nm0);
            sacc[nt].z = __expf(sacc[nt].z - nm1);
            sacc[nt].w = __expf(sacc[nt].w - nm1);
            s0 += sacc[nt].x + sacc[nt].y;
            s1 += sacc[nt].z + sacc[nt].w;
        }
        s0 += __shfl_xor_sync(0xffffffffu, s0, 1);
        s0 += __shfl_xor_sync(0xffffffffu, s0, 2);
        s1 += __shfl_xor_sync(0xffffffffu, s1, 1);
        s1 += __shfl_xor_sync(0xffffffffu, s1, 2);
        lr0 = lr0 * cr0 + s0;
        lr1 = lr1 * cr1 + s1;
#pragma unroll
        for (int nt = 0; nt < 8; nt++) {
            oacc[nt].x *= cr0; oacc[nt].y *= cr0;
            oacc[nt].z *= cr1; oacc[nt].w *= cr1;
        }

        // O += P V : P converts C-frag -> fp16 A-frag purely in registers
#pragma unroll
        for (int kt = 0; kt < 8; kt++) {
            unsigned a[4];
            a[0] = packh2(sacc[2 * kt].x,     sacc[2 * kt].y);
            a[1] = packh2(sacc[2 * kt].z,     sacc[2 * kt].w);
            a[2] = packh2(sacc[2 * kt + 1].x, sacc[2 * kt + 1].y);
            a[3] = packh2(sacc[2 * kt + 1].z, sacc[2 * kt + 1].w);
#pragma unroll
            for (int nt = 0; nt < 8; nt++) {
                unsigned b0 = Vhs[(nt * 8 + g) * 68 + kt * 8 + tg];
                unsigned b1 = Vhs[(nt * 8 + g) * 68 + kt * 8 + tg + 4];
                mma16f(oacc[nt], a, b0, b1);
            }
        }
    }

    // Epilogue: normalize, transpose via smem overlay, coalesced store
    __syncthreads();                     // done with K/V smem; safe to overlay
    float* Pw = (float*)smu + w * (16 * 68);
    float il0 = 1.f / lr0, il1 = 1.f / lr1;
#pragma unroll
    for (int nt = 0; nt < 8; nt++) {
        *(float2*)&Pw[g * 68 + nt * 8 + 2 * tg] =
            make_float2(oacc[nt].x * il0, oacc[nt].y * il0);
        *(float2*)&Pw[(g + 8) * 68 + nt * 8 + 2 * tg] =
            make_float2(oacc[nt].z * il1, oacc[nt].w * il1);
    }
    __syncwarp();
    int qbase = q0 + w * 16;
#pragma unroll
    for (int rep = 0; rep < 2; rep++) {
        int d = rep * 32 + lane;
        float vals[16];
#pragma unroll
        for (int r = 0; r < 16; r++) vals[r] = Pw[r * 68 + d];
        float* op = out + (b * CDIM + p * DH + d) * NPIX + qbase;
#pragma unroll
        for (int r4 = 0; r4 < 4; r4++)
            *(float4*)&op[r4 * 4] =
                make_float4(vals[r4 * 4], vals[r4 * 4 + 1], vals[r4 * 4 + 2], vals[r4 * 4 + 3]);
    }
}

// ---------------------------------------------------------------------------
extern "C" void kernel_launch(void* const* d_in, const int* in_sizes, int n_in,
                              void* d_out, int out_size) {
    const float* x     = (const float*)d_in[0];
    const float* qkv_w = (const float*)d_in[1];
    const float* h_pos = (const float*)d_in[2];
    const float* w_pos = (const float*)d_in[3];
    float* out = (float*)d_out;

    static int smem_set = 0;
    const int attn_smem = (2 * 32 * 136 + 64 * 68) * (int)sizeof(unsigned);  // 52224
    if (!smem_set) {
        cudaFuncSetAttribute(attn_kernel, cudaFuncAttributeMaxDynamicSharedMemorySize, attn_smem);
        smem_set = 1;
    }

    rp_kernel<<<(CDIM * NPIX + 255) / 256, 256>>>(h_pos, w_pos);
    prep_w<<<(OC * 64 + 255) / 256, 256>>>(qkv_w);
    prep_x<<<(BATCH * 256 * 256 + 255) / 256, 256>>>(x);

    dim3 g2(NPIX / 128, OC / 128, BATCH);   // 8 x 12 x 32
    qkv_kernel<<<g2, 256>>>();

    dim3 g3(NPIX / 128, HEADS, BATCH);      // 8 x 8 x 32
    attn_kernel<<<g3, 256, attn_smem>>>(out);
}

// round 10
// speedup vs baseline: 3.7963x; 1.1778x over previous
#include <cuda_runtime.h>
#include <cuda_bf16.h>
#include <cuda_fp16.h>

#define BATCH 32
#define CDIM  512
#define LSIZE 32
#define NPIX  1024
#define HEADS 8
#define DH    64
#define OC    1536

// ---------------------------------------------------------------------------
// Device scratch (pre-split packed forms; pairs packed along the k-dim)
// ---------------------------------------------------------------------------
__device__ float    g_rp[CDIM * NPIX];
__device__ unsigned g_Wh[OC * CDIM / 2];
__device__ unsigned g_Wl[OC * CDIM / 2];
__device__ unsigned g_Xh[BATCH * (CDIM / 2) * NPIX];
__device__ unsigned g_Xl[BATCH * (CDIM / 2) * NPIX];
__device__ unsigned g_Qh[BATCH * (CDIM / 2) * NPIX];
__device__ unsigned g_Ql[BATCH * (CDIM / 2) * NPIX];
__device__ unsigned g_Kh[BATCH * (CDIM / 2) * NPIX];
__device__ unsigned g_Kl[BATCH * (CDIM / 2) * NPIX];
__device__ unsigned g_Vh[BATCH * CDIM * (NPIX / 2)];

// ---------------------------------------------------------------------------
// helpers
// ---------------------------------------------------------------------------
__device__ __forceinline__ void split2(float x0, float x1, unsigned& h, unsigned& l) {
    __nv_bfloat16 h0 = __float2bfloat16(x0);
    __nv_bfloat16 h1 = __float2bfloat16(x1);
    __nv_bfloat16 l0 = __float2bfloat16(x0 - __bfloat162float(h0));
    __nv_bfloat16 l1 = __float2bfloat16(x1 - __bfloat162float(h1));
    h = ((unsigned)__bfloat16_as_ushort(h1) << 16) | __bfloat16_as_ushort(h0);
    l = ((unsigned)__bfloat16_as_ushort(l1) << 16) | __bfloat16_as_ushort(l0);
}
__device__ __forceinline__ unsigned packh2(float x0, float x1) {
    __half2 h = __floats2half2_rn(x0, x1);
    return *(unsigned*)&h;
}
__device__ __forceinline__ void mma16(float4& c, const unsigned* a, unsigned b0, unsigned b1) {
    asm volatile(
        "mma.sync.aligned.m16n8k16.row.col.f32.bf16.bf16.f32 "
        "{%0,%1,%2,%3}, {%4,%5,%6,%7}, {%8,%9}, {%0,%1,%2,%3};"
        : "+f"(c.x), "+f"(c.y), "+f"(c.z), "+f"(c.w)
        : "r"(a[0]), "r"(a[1]), "r"(a[2]), "r"(a[3]), "r"(b0), "r"(b1));
}
__device__ __forceinline__ void mma16f(float4& c, const unsigned* a, unsigned b0, unsigned b1) {
    asm volatile(
        "mma.sync.aligned.m16n8k16.row.col.f32.f16.f16.f32 "
        "{%0,%1,%2,%3}, {%4,%5,%6,%7}, {%8,%9}, {%0,%1,%2,%3};"
        : "+f"(c.x), "+f"(c.y), "+f"(c.z), "+f"(c.w)
        : "r"(a[0]), "r"(a[1]), "r"(a[2]), "r"(a[3]), "r"(b0), "r"(b1));
}
__device__ __forceinline__ unsigned sptr(const void* p) {
    return (unsigned)__cvta_generic_to_shared(p);
}
__device__ __forceinline__ void cpa16(unsigned dst, const void* src) {
    asm volatile("cp.async.cg.shared.global [%0], [%1], 16;" :: "r"(dst), "l"(src));
}
#define CP_COMMIT() asm volatile("cp.async.commit_group;")
#define CP_WAIT0()  asm volatile("cp.async.wait_group 0;")

// ---------------------------------------------------------------------------
// Kernel 1: rp table
// ---------------------------------------------------------------------------
__global__ void rp_kernel(const float* __restrict__ h_pos,
                          const float* __restrict__ w_pos) {
    int i = blockIdx.x * blockDim.x + threadIdx.x;
    if (i >= CDIM * NPIX) return;
    int m = i & (NPIX - 1);
    int c = i >> 10;
    g_rp[i] = h_pos[(m >> 5) * CDIM + c] + w_pos[(m & 31) * CDIM + c];
}

// ---------------------------------------------------------------------------
// Prep kernels (one-time split)
// ---------------------------------------------------------------------------
__global__ void prep_w(const float* __restrict__ wmat) {
    int i = blockIdx.x * blockDim.x + threadIdx.x;
    if (i >= OC * 64) return;
    int o  = i >> 6;
    int c8 = (i & 63) * 8;
    float4 a = *(const float4*)&wmat[o * CDIM + c8];
    float4 b = *(const float4*)&wmat[o * CDIM + c8 + 4];
    uint4 H, L;
    split2(a.x, a.y, H.x, L.x); split2(a.z, a.w, H.y, L.y);
    split2(b.x, b.y, H.z, L.z); split2(b.z, b.w, H.w, L.w);
    ((uint4*)g_Wh)[i] = H;
    ((uint4*)g_Wl)[i] = L;
}

__global__ void prep_x(const float* __restrict__ x) {
    int i = blockIdx.x * blockDim.x + threadIdx.x;
    if (i >= BATCH * 256 * 256) return;
    int bj  = i >> 8;
    int hw4 = (i & 255) * 4;
    const float* r0 = &x[(bj * 2) * NPIX + hw4];
    float4 u = *(const float4*)r0;
    float4 v = *(const float4*)(r0 + NPIX);
    uint4 H, L;
    split2(u.x, v.x, H.x, L.x); split2(u.y, v.y, H.y, L.y);
    split2(u.z, v.z, H.z, L.z); split2(u.w, v.w, H.w, L.w);
    ((uint4*)g_Xh)[i] = H;
    ((uint4*)g_Xl)[i] = L;
}

// ---------------------------------------------------------------------------
// Kernel 2: QKV GEMM, bf16x3 mma, cp.async double-buffered.
// 128(o) x 128(hw) tile, 8 warps (4M x 2N).
// ---------------------------------------------------------------------------
__global__ __launch_bounds__(256) void qkv_kernel() {
    __shared__ unsigned Ah[2][128][12], Al[2][128][12];   // kp 0..7, pad 12
    __shared__ unsigned Bh[2][8][136],  Bl[2][8][136];

    const int b   = blockIdx.z;
    const int oc0 = blockIdx.y * 128;
    const int hw0 = blockIdx.x * 128;
    const int tid = threadIdx.x;
    const int w   = tid >> 5, lane = tid & 31;
    const int g   = lane >> 2, tg = lane & 3;
    const int wm  = w & 3, wn = w >> 2;

    float4 acc[2][8];
#pragma unroll
    for (int i = 0; i < 2; i++)
#pragma unroll
        for (int j = 0; j < 8; j++) acc[i][j] = make_float4(0.f, 0.f, 0.f, 0.f);

    const int ar  = tid >> 1;          // A row 0..127
    const int ak4 = (tid & 1) * 4;     // kp offset 0/4
    const int bj  = tid >> 5;          // B kp row 0..7
    const int bn4 = (tid & 31) * 4;

    auto load_stage = [&](int st, int cp0) {
        cpa16(sptr(&Ah[st][ar][ak4]), &g_Wh[(oc0 + ar) * 256 + cp0 + ak4]);
        cpa16(sptr(&Al[st][ar][ak4]), &g_Wl[(oc0 + ar) * 256 + cp0 + ak4]);
        cpa16(sptr(&Bh[st][bj][bn4]), &g_Xh[(b * 256 + cp0 + bj) * NPIX + hw0 + bn4]);
        cpa16(sptr(&Bl[st][bj][bn4]), &g_Xl[(b * 256 + cp0 + bj) * NPIX + hw0 + bn4]);
        CP_COMMIT();
    };

    load_stage(0, 0);

    for (int s = 0; s < 32; s++) {
        CP_WAIT0();
        __syncthreads();
        if (s + 1 < 32) load_stage((s + 1) & 1, (s + 1) * 8);

        const int st = s & 1;
        unsigned ah[2][4], al[2][4];
#pragma unroll
        for (int mt = 0; mt < 2; mt++) {
            int mr = wm * 32 + mt * 16 + g;
            ah[mt][0] = Ah[st][mr][tg];         al[mt][0] = Al[st][mr][tg];
            ah[mt][1] = Ah[st][mr + 8][tg];     al[mt][1] = Al[st][mr + 8][tg];
            ah[mt][2] = Ah[st][mr][tg + 4];     al[mt][2] = Al[st][mr][tg + 4];
            ah[mt][3] = Ah[st][mr + 8][tg + 4]; al[mt][3] = Al[st][mr + 8][tg + 4];
        }
#pragma unroll
        for (int nt = 0; nt < 8; nt++) {
            int n = wn * 64 + nt * 8 + g;
            unsigned bh0 = Bh[st][tg][n], bh1 = Bh[st][tg + 4][n];
            unsigned bl0 = Bl[st][tg][n], bl1 = Bl[st][tg + 4][n];
#pragma unroll
            for (int mt = 0; mt < 2; mt++) {
                mma16(acc[mt][nt], ah[mt], bh0, bh1);
                mma16(acc[mt][nt], ah[mt], bl0, bl1);
                mma16(acc[mt][nt], al[mt], bh0, bh1);
            }
        }
    }

    // Epilogue: which 0=Q, 1=K(+rp), 2=V. Write split-packed global forms.
    const int which = oc0 >> 9;

#pragma unroll
    for (int mt = 0; mt < 2; mt++)
#pragma unroll
        for (int half = 0; half < 2; half++) {
            int o  = oc0 + wm * 32 + mt * 16 + g + half * 8;
            int oo = o & 511;
#pragma unroll
            for (int nt = 0; nt < 8; nt++) {
                int hw = hw0 + wn * 64 + nt * 8 + 2 * tg;
                float2 v = half ? make_float2(acc[mt][nt].z, acc[mt][nt].w)
                                : make_float2(acc[mt][nt].x, acc[mt][nt].y);
                if (which == 2) {
                    g_Vh[(b * 512 + oo) * 512 + (hw >> 1)] = packh2(v.x, v.y);
                } else {
                    if (which == 1) {
                        float2 r = *(const float2*)&g_rp[oo * NPIX + hw];
                        v.x += r.x; v.y += r.y;
                    }
                    float px = __shfl_xor_sync(0xffffffffu, v.x, 4);
                    float py = __shfl_xor_sync(0xffffffffu, v.y, 4);
                    if (!(g & 1)) {
                        unsigned h0, l0, h1, l1;
                        split2(v.x, px, h0, l0);
                        split2(v.y, py, h1, l1);
                        unsigned* dh = which ? g_Kh : g_Qh;
                        unsigned* dl = which ? g_Kl : g_Ql;
                        int base = (b * 256 + (oo >> 1)) * NPIX + hw;
                        *(uint2*)&dh[base] = make_uint2(h0, h1);
                        *(uint2*)&dl[base] = make_uint2(l0, l1);
                    }
                }
            }
        }
}

// ---------------------------------------------------------------------------
// Kernel 3: flash attention, cp.async double-buffered tiles.
// S = QK'^T bf16x3, PV fp16 (P in registers). 128 q/block, 128-key tiles.
// Stage layout (words): Kh[32][136] | Kl[32][136] | Vh[64][68]  = 13056
// ---------------------------------------------------------------------------
#define AST 13056

__global__ __launch_bounds__(256) void attn_kernel(float* __restrict__ out) {
    extern __shared__ unsigned smu[];

    const int b = blockIdx.z, p = blockIdx.y;
    const int tid  = threadIdx.x;
    const int w    = tid >> 5, lane = tid & 31;
    const int g    = lane >> 2, tg = lane & 3;
    const int q0   = blockIdx.x * 128;
    const int bp32 = b * 256 + p * 32;
    const int vb   = b * 512 + p * 64;

    auto load_tile = [&](int st, int kv) {
        unsigned* Khs = smu + st * AST;
        unsigned* Kls = Khs + 32 * 136;
        unsigned* Vhs = Kls + 32 * 136;
#pragma unroll
        for (int t = 0; t < 4; t++) {
            int i  = tid + t * 256;
            int dp = i >> 5;
            int k4 = (i & 31) * 4;
            cpa16(sptr(&Khs[dp * 136 + k4]), &g_Kh[(bp32 + dp) * NPIX + kv + k4]);
            cpa16(sptr(&Kls[dp * 136 + k4]), &g_Kl[(bp32 + dp) * NPIX + kv + k4]);
        }
#pragma unroll
        for (int t = 0; t < 4; t++) {
            int i   = tid + t * 256;
            int d   = i >> 4;
            int kp4 = (i & 15) * 4;
            cpa16(sptr(&Vhs[d * 68 + kp4]), &g_Vh[(vb + d) * 512 + (kv >> 1) + kp4]);
        }
        CP_COMMIT();
    };

    // Q A-fragments from pre-split globals
    unsigned qh[4][4], ql[4][4];
    {
        int qr = q0 + w * 16 + g;
#pragma unroll
        for (int kt = 0; kt < 4; kt++)
#pragma unroll
            for (int r = 0; r < 4; r++) {
                int row = qr + ((r & 1) ? 8 : 0);
                int dp  = kt * 8 + tg + ((r & 2) ? 4 : 0);
                qh[kt][r] = g_Qh[(bp32 + dp) * NPIX + row];
                ql[kt][r] = g_Ql[(bp32 + dp) * NPIX + row];
            }
    }

    float4 oacc[8];
#pragma unroll
    for (int i = 0; i < 8; i++) oacc[i] = make_float4(0.f, 0.f, 0.f, 0.f);
    float mr0 = -1e30f, mr1 = -1e30f, lr0 = 0.f, lr1 = 0.f;

    load_tile(0, 0);

    for (int s = 0; s < 8; s++) {
        CP_WAIT0();
        __syncthreads();
        if (s < 7) load_tile((s + 1) & 1, (s + 1) * 128);

        unsigned* Khs = smu + (s & 1) * AST;
        unsigned* Kls = Khs + 32 * 136;
        unsigned* Vhs = Kls + 32 * 136;

        // S = Q K'^T, bf16x3
        float4 sacc[16];
#pragma unroll
        for (int i = 0; i < 16; i++) sacc[i] = make_float4(0.f, 0.f, 0.f, 0.f);
#pragma unroll
        for (int kt = 0; kt < 4; kt++) {
#pragma unroll
            for (int nt = 0; nt < 16; nt++) {
                int n = nt * 8 + g;
                unsigned bh0 = Khs[(kt * 8 + tg) * 136 + n];
                unsigned bh1 = Khs[(kt * 8 + tg + 4) * 136 + n];
                unsigned bl0 = Kls[(kt * 8 + tg) * 136 + n];
                unsigned bl1 = Kls[(kt * 8 + tg + 4) * 136 + n];
                mma16(sacc[nt], qh[kt], bh0, bh1);
                mma16(sacc[nt], qh[kt], bl0, bl1);
                mma16(sacc[nt], ql[kt], bh0, bh1);
            }
        }

        // Online softmax (rows g, g+8); sacc overwritten with exp weights
        float rm0 = -1e30f, rm1 = -1e30f;
#pragma unroll
        for (int nt = 0; nt < 16; nt++) {
            rm0 = fmaxf(rm0, fmaxf(sacc[nt].x, sacc[nt].y));
            rm1 = fmaxf(rm1, fmaxf(sacc[nt].z, sacc[nt].w));
        }
        rm0 = fmaxf(rm0, __shfl_xor_sync(0xffffffffu, rm0, 1));
        rm0 = fmaxf(rm0, __shfl_xor_sync(0xffffffffu, rm0, 2));
        rm1 = fmaxf(rm1, __shfl_xor_sync(0xffffffffu, rm1, 1));
        rm1 = fmaxf(rm1, __shfl_xor_sync(0xffffffffu, rm1, 2));
        float nm0 = fmaxf(mr0, rm0), nm1 = fmaxf(mr1, rm1);
        float cr0 = __expf(mr0 - nm0), cr1 = __expf(mr1 - nm1);
        mr0 = nm0; mr1 = nm1;

        float s0 = 0.f, s1 = 0.f;
#pragma unroll
        for (int nt = 0; nt < 16; nt++) {
            sacc[nt].x = __expf(sacc[nt].x - nm0);
            sacc[nt].y = __expf(sacc[nt].y - nm0);
            sacc[nt].z = __expf(sacc[nt].z - nm1);
            sacc[nt].w = __expf(sacc[nt].w - nm1);
            s0 += sacc[nt].x + sacc[nt].y;
            s1 += sacc[nt].z + sacc[nt].w;
        }
        s0 += __shfl_xor_sync(0xffffffffu, s0, 1);
        s0 += __shfl_xor_sync(0xffffffffu, s0, 2);
        s1 += __shfl_xor_sync(0xffffffffu, s1, 1);
        s1 += __shfl_xor_sync(0xffffffffu, s1, 2);
        lr0 = lr0 * cr0 + s0;
        lr1 = lr1 * cr1 + s1;
#pragma unroll
        for (int nt = 0; nt < 8; nt++) {
            oacc[nt].x *= cr0; oacc[nt].y *= cr0;
            oacc[nt].z *= cr1; oacc[nt].w *= cr1;
        }

        // O += P V : C-frag -> fp16 A-frag in registers
#pragma unroll
        for (int kt = 0; kt < 8; kt++) {
            unsigned a[4];
            a[0] = packh2(sacc[2 * kt].x,     sacc[2 * kt].y);
            a[1] = packh2(sacc[2 * kt].z,     sacc[2 * kt].w);
            a[2] = packh2(sacc[2 * kt + 1].x, sacc[2 * kt + 1].y);
            a[3] = packh2(sacc[2 * kt + 1].z, sacc[2 * kt + 1].w);
#pragma unroll
            for (int nt = 0; nt < 8; nt++) {
                unsigned b0 = Vhs[(nt * 8 + g) * 68 + kt * 8 + tg];
                unsigned b1 = Vhs[(nt * 8 + g) * 68 + kt * 8 + tg + 4];
                mma16f(oacc[nt], a, b0, b1);
            }
        }
    }

    // Epilogue: normalize, transpose via smem overlay, coalesced store
    __syncthreads();
    float* Pw = (float*)smu + w * (16 * 68);
    float il0 = 1.f / lr0, il1 = 1.f / lr1;
#pragma unroll
    for (int nt = 0; nt < 8; nt++) {
        *(float2*)&Pw[g * 68 + nt * 8 + 2 * tg] =
            make_float2(oacc[nt].x * il0, oacc[nt].y * il0);
        *(float2*)&Pw[(g + 8) * 68 + nt * 8 + 2 * tg] =
            make_float2(oacc[nt].z * il1, oacc[nt].w * il1);
    }
    __syncwarp();
    int qbase = q0 + w * 16;
#pragma unroll
    for (int rep = 0; rep < 2; rep++) {
        int d = rep * 32 + lane;
        float vals[16];
#pragma unroll
        for (int r = 0; r < 16; r++) vals[r] = Pw[r * 68 + d];
        float* op = out + (b * CDIM + p * DH + d) * NPIX + qbase;
#pragma unroll
        for (int r4 = 0; r4 < 4; r4++)
            *(float4*)&op[r4 * 4] =
                make_float4(vals[r4 * 4], vals[r4 * 4 + 1], vals[r4 * 4 + 2], vals[r4 * 4 + 3]);
    }
}

// ---------------------------------------------------------------------------
extern "C" void kernel_launch(void* const* d_in, const int* in_sizes, int n_in,
                              void* d_out, int out_size) {
    const float* x     = (const float*)d_in[0];
    const float* qkv_w = (const float*)d_in[1];
    const float* h_pos = (const float*)d_in[2];
    const float* w_pos = (const float*)d_in[3];
    float* out = (float*)d_out;

    static int smem_set = 0;
    const int attn_smem = 2 * AST * (int)sizeof(unsigned);   // 104448
    if (!smem_set) {
        cudaFuncSetAttribute(attn_kernel, cudaFuncAttributeMaxDynamicSharedMemorySize, attn_smem);
        smem_set = 1;
    }

    rp_kernel<<<(CDIM * NPIX + 255) / 256, 256>>>(h_pos, w_pos);
    prep_w<<<(OC * 64 + 255) / 256, 256>>>(qkv_w);
    prep_x<<<(BATCH * 256 * 256 + 255) / 256, 256>>>(x);

    dim3 g2(NPIX / 128, OC / 128, BATCH);   // 8 x 12 x 32
    qkv_kernel<<<g2, 256>>>();

    dim3 g3(NPIX / 128, HEADS, BATCH);      // 8 x 8 x 32
    attn_kernel<<<g3, 256, attn_smem>>>(out);
}